// round 1
// baseline (speedup 1.0000x reference)
#include <cuda_runtime.h>
#include <cstdint>

#define AANCH 69354
#define APAD  69376
#define NCLS  80
#define TOPK  1000
#define CAND  2048
#define NB    8192
#define SCORE_TH 0.05f
#define IOU_TH   0.5f

typedef unsigned int u32;
typedef unsigned long long u64;

// ---- device scratch (no allocations allowed) ----
__device__ float g_boxes[AANCH * 4];
__device__ float g_scoresT[(size_t)NCLS * APAD];

// ---- shared memory layout for per-class kernel (bytes) ----
// region [0,128000): suppression mask (1000 rows x 32 u32)
//   aliased early by: hist u32[8192] @0 (32768B), keys u64[2048] @32768 (16384B)
// persistent region @128000:
#define OFF_HIST   0
#define OFF_KEYS   32768
#define OFF_MASK   0
#define OFF_SX1    128000
#define OFF_SY1    132000
#define OFF_SX2    136000
#define OFF_SY2    140000
#define OFF_SAR    144000
#define OFF_SSC    148000
#define OFF_VALW   152000
#define OFF_KEEPW  152128
#define OFF_CSUM   152256
#define OFF_MISC   153280
#define SMEM_TOTAL 153344

// ============================================================
// Kernel 1: decode + clip boxes
// ============================================================
__global__ void decode_kernel(const float* __restrict__ anchors,
                              const float* __restrict__ regr,
                              const int* __restrict__ ph,
                              const int* __restrict__ pw) {
    int a = blockIdx.x * blockDim.x + threadIdx.x;
    if (a >= AANCH) return;
    float W = pw ? (float)(*pw) : 608.0f;
    float H = ph ? (float)(*ph) : 608.0f;
    float4 an = ((const float4*)anchors)[a];
    float4 dl = ((const float4*)regr)[a];
    float w = an.z - an.x;
    float h = an.w - an.y;
    float cx = an.x + 0.5f * w;
    float cy = an.y + 0.5f * h;
    float dx = dl.x * 0.1f, dy = dl.y * 0.1f;
    float dw = dl.z * 0.2f, dh = dl.w * 0.2f;
    float pcx = cx + dx * w;
    float pcy = cy + dy * h;
    float pwid = expf(dw) * w;
    float phgt = expf(dh) * h;
    float x1 = fminf(fmaxf(pcx - 0.5f * pwid, 0.0f), W);
    float y1 = fminf(fmaxf(pcy - 0.5f * phgt, 0.0f), H);
    float x2 = fminf(fmaxf(pcx + 0.5f * pwid, 0.0f), W);
    float y2 = fminf(fmaxf(pcy + 0.5f * phgt, 0.0f), H);
    ((float4*)g_boxes)[a] = make_float4(x1, y1, x2, y2);
}

// ============================================================
// Kernel 2: transpose classification [A,80] -> g_scoresT [80,APAD]
// ============================================================
__global__ void transpose_kernel(const float* __restrict__ cls) {
    __shared__ float tile[32][33];
    int a0 = blockIdx.x * 32;
    int c0 = blockIdx.y * 32;
    int tx = threadIdx.x, ty = threadIdx.y;
#pragma unroll
    for (int r = 0; r < 32; r += 8) {
        int a = a0 + ty + r, c = c0 + tx;
        float v = -1.0f;
        if (a < AANCH && c < NCLS) v = cls[(size_t)a * NCLS + c];
        tile[ty + r][tx] = v;
    }
    __syncthreads();
#pragma unroll
    for (int r = 0; r < 32; r += 8) {
        int c = c0 + ty + r, a = a0 + tx;
        if (c < NCLS && a < APAD) g_scoresT[(size_t)c * APAD + a] = tile[tx][ty + r];
    }
}

// ============================================================
// Kernel 3: per-class top-K + NMS + output. grid=80, block=256.
// ============================================================
__global__ void __launch_bounds__(256, 1)
perclass_kernel(float* __restrict__ out, int out_size) {
    extern __shared__ char sm[];
    u32*  hist  = (u32*)(sm + OFF_HIST);
    u64*  keys  = (u64*)(sm + OFF_KEYS);
    u32*  maskS = (u32*)(sm + OFF_MASK);
    float* sx1 = (float*)(sm + OFF_SX1);
    float* sy1 = (float*)(sm + OFF_SY1);
    float* sx2 = (float*)(sm + OFF_SX2);
    float* sy2 = (float*)(sm + OFF_SY2);
    float* sar = (float*)(sm + OFF_SAR);
    float* ssc = (float*)(sm + OFF_SSC);
    u32*  validW = (u32*)(sm + OFF_VALW);
    u32*  keepW  = (u32*)(sm + OFF_KEEPW);
    u32*  csum   = (u32*)(sm + OFF_CSUM);
    int*  misc   = (int*)(sm + OFF_MISC);

    const int c = blockIdx.x;
    const int tid = threadIdx.x;
    const float* row = g_scoresT + (size_t)c * APAD;

    // ---- Stage A: histogram of valid scores ----
    for (int b = tid; b < NB; b += 256) hist[b] = 0;
    __syncthreads();
    for (int a = tid; a < AANCH; a += 256) {
        float s = row[a];
        if (s > SCORE_TH) {
            int b = (int)(s * (NB / 0.25f));
            b = min(b, NB - 1);
            atomicAdd(&hist[b], 1u);
        }
    }
    __syncthreads();

    // ---- Stage B: find cutoff bin (bucket >= cut keeps >= min(TOPK, total)) ----
    {
        const int per = NB / 256;  // 32 bins per thread
        u32 acc = 0;
#pragma unroll
        for (int u = 0; u < per; u++) acc += hist[tid * per + u];
        csum[tid] = acc;
        __syncthreads();
        if (tid == 0) {
            int cut = 0;
            u32 tot = 0;
            for (int cj = 255; cj >= 0; cj--) {
                if (tot + csum[cj] >= (u32)TOPK) {
                    int base = cj * per;
                    for (int b = base + per - 1; b >= base; b--) {
                        tot += hist[b];
                        if (tot >= (u32)TOPK) { cut = b; break; }
                    }
                    break;
                }
                tot += csum[cj];
            }
            misc[0] = cut;
            misc[1] = 0;
        }
    }
    __syncthreads();
    const int cut = misc[0];

    // ---- Stage C: gather candidate keys ----
    for (int i = tid; i < CAND; i += 256) keys[i] = 0ull;
    __syncthreads();
    for (int a = tid; a < AANCH; a += 256) {
        float s = row[a];
        if (s > SCORE_TH) {
            int b = (int)(s * (NB / 0.25f));
            b = min(b, NB - 1);
            if (b >= cut) {
                int p = atomicAdd(&misc[1], 1);
                if (p < CAND) {
                    keys[p] = ((u64)__float_as_uint(s) << 32) | (u32)(~(u32)a);
                }
            }
        }
    }
    __syncthreads();

    // ---- Stage D: bitonic sort descending (key = score bits desc, idx asc) ----
    for (int k = 2; k <= CAND; k <<= 1) {
        for (int j = k >> 1; j > 0; j >>= 1) {
#pragma unroll
            for (int p = 0; p < CAND / 256; p++) {
                int i = tid + p * 256;
                int ixj = i ^ j;
                if (ixj > i) {
                    u64 va = keys[i], vb = keys[ixj];
                    bool up = ((i & k) == 0);
                    if ((va < vb) == up) { keys[i] = vb; keys[ixj] = va; }
                }
            }
            __syncthreads();
        }
    }

    // ---- Stage E: extract top-1000, gather boxes, set valid bits ----
#pragma unroll
    for (int p = 0; p < 4; p++) {
        int k = tid + p * 256;  // 0..1023
        bool valid = false;
        float sc = -1.0f, x1 = 0.f, y1 = 0.f, x2 = 0.f, y2 = 0.f, ar = 0.f;
        if (k < TOPK) {
            u64 key = keys[k];
            if (key != 0ull) {
                valid = true;
                sc = __uint_as_float((u32)(key >> 32));
                u32 a = ~(u32)key;
                float4 bx = ((const float4*)g_boxes)[a];
                x1 = bx.x; y1 = bx.y; x2 = bx.z; y2 = bx.w;
                ar = (x2 - x1) * (y2 - y1);
            }
            sx1[k] = x1; sy1[k] = y1; sx2[k] = x2; sy2[k] = y2;
            sar[k] = ar; ssc[k] = sc;
        }
        u32 bal = __ballot_sync(0xffffffffu, valid);
        if ((tid & 31) == 0) validW[k >> 5] = bal;
    }
    __syncthreads();

    // ---- Stage F: suppression mask (upper triangle, row-per-warp) ----
    for (int i = tid; i < TOPK * 32; i += 256) maskS[i] = 0;
    __syncthreads();
    {
        const int warp = tid >> 5, lane = tid & 31;
        for (int i = warp; i < TOPK; i += 8) {
            float ix1 = sx1[i], iy1 = sy1[i], ix2 = sx2[i], iy2 = sy2[i], iar = sar[i];
            for (int w = (i >> 5); w < 32; w++) {
                int j = w * 32 + lane;
                bool sup = false;
                if (j > i && j < TOPK) {
                    float xx1 = fmaxf(ix1, sx1[j]);
                    float yy1 = fmaxf(iy1, sy1[j]);
                    float xx2 = fminf(ix2, sx2[j]);
                    float yy2 = fminf(iy2, sy2[j]);
                    float iw = fmaxf(xx2 - xx1, 0.0f);
                    float ih = fmaxf(yy2 - yy1, 0.0f);
                    float inter = iw * ih;
                    float iou = inter / (iar + sar[j] - inter + 1e-8f);
                    sup = (iou > IOU_TH);
                }
                u32 word = __ballot_sync(0xffffffffu, sup);
                if (lane == 0) maskS[i * 32 + w] = word;
            }
        }
    }
    __syncthreads();

    // ---- Stage G: sequential greedy scan (warp 0, remv in registers) ----
    if (tid < 32) {
        const int lane = tid;
        u32 remv = ~validW[lane];
        u32 keepw = 0;
        u32 rowreg = maskS[lane];  // row 0 prefetch
        for (int i = 0; i < TOPK; i++) {
            int w = i >> 5, b = i & 31;
            u32 rv = __shfl_sync(0xffffffffu, remv, w);
            u32 nxt = (i < TOPK - 1) ? maskS[(i + 1) * 32 + lane] : 0u;
            if (!((rv >> b) & 1u)) {
                remv |= rowreg;
                if (lane == w) keepw |= (1u << b);
            }
            rowreg = nxt;
        }
        keepW[lane] = keepw;
    }
    __syncthreads();

    // ---- Stage H: write detections ----
    for (int k = tid; k < TOPK; k += 256) {
        bool kp = (keepW[k >> 5] >> (k & 31)) & 1u;
        size_t o = ((size_t)c * TOPK + k) * 5;
        if (o + 5 <= (size_t)out_size) {
            out[o + 0] = kp ? ssc[k] : -1.0f;
            out[o + 1] = kp ? sx1[k] : 0.0f;
            out[o + 2] = kp ? sy1[k] : 0.0f;
            out[o + 3] = kp ? sx2[k] : 0.0f;
            out[o + 4] = kp ? sy2[k] : 0.0f;
        }
    }
}

// ============================================================
// Kernel 4: class ids (+ zero any tail)
// ============================================================
__global__ void finalize_kernel(float* __restrict__ out, int out_size) {
    int g = 400000 + blockIdx.x * blockDim.x + threadIdx.x;
    if (g < out_size) {
        if (g < 480000) out[g] = (float)((g - 400000) / 1000);
        else            out[g] = 0.0f;
    }
}

// ============================================================
extern "C" void kernel_launch(void* const* d_in, const int* in_sizes, int n_in,
                              void* d_out, int out_size) {
    const float* cls     = (const float*)d_in[0];
    const float* regr    = (const float*)d_in[1];
    const float* anchors = (const float*)d_in[2];
    const int* ph = (n_in > 3) ? (const int*)d_in[3] : nullptr;
    const int* pw = (n_in > 4) ? (const int*)d_in[4] : nullptr;
    float* out = (float*)d_out;

    static bool attr_set = false;
    if (!attr_set) {
        cudaFuncSetAttribute(perclass_kernel,
                             cudaFuncAttributeMaxDynamicSharedMemorySize,
                             SMEM_TOTAL);
        attr_set = true;
    }

    decode_kernel<<<(AANCH + 255) / 256, 256>>>(anchors, regr, ph, pw);
    {
        dim3 grid(APAD / 32, (NCLS + 31) / 32);
        dim3 block(32, 8);
        transpose_kernel<<<grid, block>>>(cls);
    }
    perclass_kernel<<<NCLS, 256, SMEM_TOTAL>>>(out, out_size);
    if (out_size > 400000) {
        int n = out_size - 400000;
        finalize_kernel<<<(n + 255) / 256, 256>>>(out, out_size);
    }
}

// round 2
// speedup vs baseline: 1.8161x; 1.8161x over previous
#include <cuda_runtime.h>
#include <cstdint>

#define AANCH 69354
#define APAD  69376
#define NCLS  80
#define TOPK  1000
#define KPAD  1024
#define CAND  2048
#define SCORE_TH 0.05f
#define IOU_TH   0.5f

typedef unsigned int u32;
typedef unsigned long long u64;

// ---- device scratch (no allocations allowed) ----
__device__ float g_boxes[AANCH * 4];
__device__ float g_scoresT[(size_t)NCLS * APAD];
__device__ float g_cx1[NCLS * KPAD];
__device__ float g_cy1[NCLS * KPAD];
__device__ float g_cx2[NCLS * KPAD];
__device__ float g_cy2[NCLS * KPAD];
__device__ float g_car[NCLS * KPAD];
__device__ float g_csc[NCLS * KPAD];
__device__ u32   g_valid[NCLS * 32];
__device__ u32   g_mask[(size_t)NCLS * TOPK * 32];   // 10.24 MB

// ============================================================
// Kernel 1: decode + clip boxes
// ============================================================
__global__ void decode_kernel(const float* __restrict__ anchors,
                              const float* __restrict__ regr,
                              const int* __restrict__ ph,
                              const int* __restrict__ pw) {
    int a = blockIdx.x * blockDim.x + threadIdx.x;
    if (a >= AANCH) return;
    float W = pw ? (float)(*pw) : 608.0f;
    float H = ph ? (float)(*ph) : 608.0f;
    float4 an = ((const float4*)anchors)[a];
    float4 dl = ((const float4*)regr)[a];
    float w = an.z - an.x;
    float h = an.w - an.y;
    float cx = an.x + 0.5f * w;
    float cy = an.y + 0.5f * h;
    float dx = dl.x * 0.1f, dy = dl.y * 0.1f;
    float dw = dl.z * 0.2f, dh = dl.w * 0.2f;
    float pcx = cx + dx * w;
    float pcy = cy + dy * h;
    float pwid = expf(dw) * w;
    float phgt = expf(dh) * h;
    float x1 = fminf(fmaxf(pcx - 0.5f * pwid, 0.0f), W);
    float y1 = fminf(fmaxf(pcy - 0.5f * phgt, 0.0f), H);
    float x2 = fminf(fmaxf(pcx + 0.5f * pwid, 0.0f), W);
    float y2 = fminf(fmaxf(pcy + 0.5f * phgt, 0.0f), H);
    ((float4*)g_boxes)[a] = make_float4(x1, y1, x2, y2);
}

// ============================================================
// Kernel 2: transpose classification [A,80] -> g_scoresT [80,APAD]
// ============================================================
__global__ void transpose_kernel(const float* __restrict__ cls) {
    __shared__ float tile[32][33];
    int a0 = blockIdx.x * 32;
    int c0 = blockIdx.y * 32;
    int tx = threadIdx.x, ty = threadIdx.y;
#pragma unroll
    for (int r = 0; r < 32; r += 8) {
        int a = a0 + ty + r, c = c0 + tx;
        float v = -1.0f;
        if (a < AANCH && c < NCLS) v = cls[(size_t)a * NCLS + c];
        tile[ty + r][tx] = v;
    }
    __syncthreads();
#pragma unroll
    for (int r = 0; r < 32; r += 8) {
        int c = c0 + ty + r, a = a0 + tx;
        if (c < NCLS && a < APAD) g_scoresT[(size_t)c * APAD + a] = tile[tx][ty + r];
    }
}

// ============================================================
// Kernel 3: per-class exact top-1000 (ballot histogram, no atomics in the
// hot passes) + bitonic sort + candidate table write. grid=80, block=512.
// ============================================================
__device__ __forceinline__ int bin_of(float s) {
    int b = (int)((s - SCORE_TH) * (32.0f / 0.15f));
    return min(max(b, 0), 31);
}

__global__ void __launch_bounds__(512)
topk_kernel() {
    __shared__ u64 keys[CAND];
    __shared__ u32 wcnt[16][32];
    __shared__ u32 bincnt[32];
    __shared__ int s_b1, s_need, s_b2, s_cnt;

    const int c = blockIdx.x;
    const int tid = threadIdx.x, lane = tid & 31;
    const int warp = tid >> 5;
    const float* row = g_scoresT + (size_t)c * APAD;

    for (int i = tid; i < CAND; i += 512) keys[i] = 0ull;

    const int NITER = (APAD + 511) / 512;  // 136

    // ---- pass 1: 32-bin count over (TH, TH+0.15], register-resident ----
    {
        u32 cnt = 0;
        for (int it = 0; it < NITER; it++) {
            int a = tid + it * 512;
            float s = (a < APAD) ? row[a] : -1.0f;
            bool ir = s > SCORE_TH;
            int bin = ir ? bin_of(s) : 0;
            u32 m = __ballot_sync(0xffffffffu, ir);
#pragma unroll
            for (int b = 0; b < 5; b++) {
                u32 vb = __ballot_sync(0xffffffffu, (bin >> b) & 1);
                m &= ((lane >> b) & 1) ? vb : ~vb;
            }
            cnt += __popc(m);
        }
        wcnt[warp][lane] = cnt;
    }
    __syncthreads();
    if (tid < 32) {
        u32 acc = 0;
#pragma unroll
        for (int w = 0; w < 16; w++) acc += wcnt[w][tid];
        bincnt[tid] = acc;
    }
    __syncthreads();
    if (tid == 0) {
        int tot = 0, b1 = 0, found = 0;
        for (int b = 31; b >= 0; b--) {
            if (tot + (int)bincnt[b] >= TOPK) { b1 = b; found = 1; break; }
            tot += (int)bincnt[b];
        }
        s_b1 = found ? b1 : 0;
        s_need = TOPK - tot;
        s_b2 = 0;
        s_cnt = 0;
    }
    __syncthreads();
    const int b1 = s_b1;
    const float w1 = 0.15f / 32.0f;
    const float lo1 = SCORE_TH + b1 * w1;

    // ---- pass 2: 32 sub-bins inside bin b1 ----
    {
        u32 cnt = 0;
        for (int it = 0; it < NITER; it++) {
            int a = tid + it * 512;
            float s = (a < APAD) ? row[a] : -1.0f;
            bool ir = s > SCORE_TH;
            bool inb = ir && (bin_of(s) == b1);
            int sub = 0;
            if (inb) sub = min(max((int)((s - lo1) * (32.0f / w1)), 0), 31);
            u32 m = __ballot_sync(0xffffffffu, inb);
#pragma unroll
            for (int b = 0; b < 5; b++) {
                u32 vb = __ballot_sync(0xffffffffu, (sub >> b) & 1);
                m &= ((lane >> b) & 1) ? vb : ~vb;
            }
            cnt += __popc(m);
        }
        wcnt[warp][lane] = cnt;
    }
    __syncthreads();
    if (tid < 32) {
        u32 acc = 0;
#pragma unroll
        for (int w = 0; w < 16; w++) acc += wcnt[w][tid];
        bincnt[tid] = acc;
    }
    __syncthreads();
    if (tid == 0) {
        int need = s_need, tot2 = 0;
        for (int b = 31; b >= 0; b--) {
            tot2 += (int)bincnt[b];
            if (tot2 >= need) { s_b2 = b; break; }
        }
    }
    __syncthreads();
    const int b2 = s_b2;

    // ---- gather candidates (few atomics, ~1k total) ----
    for (int a = tid; a < AANCH; a += 512) {
        float s = row[a];
        if (s > SCORE_TH) {
            int bin = bin_of(s);
            bool q = (bin > b1);
            if (bin == b1) {
                int sub = min(max((int)((s - lo1) * (32.0f / w1)), 0), 31);
                q = (sub >= b2);
            }
            if (q) {
                int p = atomicAdd(&s_cnt, 1);
                if (p < CAND)
                    keys[p] = ((u64)__float_as_uint(s) << 32) | (u32)(~(u32)a);
            }
        }
    }
    __syncthreads();

    // ---- bitonic sort descending (score desc, idx asc) ----
    for (int k = 2; k <= CAND; k <<= 1) {
        for (int j = k >> 1; j > 0; j >>= 1) {
#pragma unroll
            for (int p = 0; p < CAND / 512; p++) {
                int i = tid + p * 512;
                int ixj = i ^ j;
                if (ixj > i) {
                    u64 va = keys[i], vb = keys[ixj];
                    bool up = ((i & k) == 0);
                    if ((va < vb) == up) { keys[i] = vb; keys[ixj] = va; }
                }
            }
            __syncthreads();
        }
    }

    // ---- write candidate table ----
#pragma unroll
    for (int p = 0; p < 2; p++) {
        int k = tid + p * 512;  // 0..1023
        u64 key = keys[k];
        bool valid = (k < TOPK) && (key != 0ull);
        float sc = -1.0f, x1 = 0.f, y1 = 0.f, x2 = 0.f, y2 = 0.f, ar = 0.f;
        if (valid) {
            sc = __uint_as_float((u32)(key >> 32));
            u32 a = ~(u32)key;
            float4 bx = ((const float4*)g_boxes)[a];
            x1 = bx.x; y1 = bx.y; x2 = bx.z; y2 = bx.w;
            ar = (x2 - x1) * (y2 - y1);
        }
        int o = c * KPAD + k;
        g_cx1[o] = x1; g_cy1[o] = y1; g_cx2[o] = x2; g_cy2[o] = y2;
        g_car[o] = ar; g_csc[o] = sc;
        u32 bal = __ballot_sync(0xffffffffu, valid);
        if (lane == 0) g_valid[c * 32 + (k >> 5)] = bal;
    }
}

// ============================================================
// Kernel 4: suppression mask build. grid=(80, 8), block=256.
// Row i of class c -> 32 u32 words (bit j set if i suppresses j).
// ============================================================
__global__ void __launch_bounds__(256)
mask_kernel() {
    __shared__ float bx1[TOPK], by1[TOPK], bx2[TOPK], by2[TOPK], bar[TOPK];
    const int c = blockIdx.x;
    const int chunk = blockIdx.y;
    const int tid = threadIdx.x, lane = tid & 31, warp = tid >> 5;

    for (int k = tid; k < TOPK; k += 256) {
        int o = c * KPAD + k;
        bx1[k] = g_cx1[o]; by1[k] = g_cy1[o];
        bx2[k] = g_cx2[o]; by2[k] = g_cy2[o];
        bar[k] = g_car[o];
    }
    __syncthreads();

    for (int i = chunk + 8 * warp; i < TOPK; i += 64) {
        float ix1 = bx1[i], iy1 = by1[i], ix2 = bx2[i], iy2 = by2[i], iar = bar[i];
        int wstart = i >> 5;
        u32* mrow = g_mask + ((size_t)(c * TOPK + i)) * 32;
        if (lane < wstart) mrow[lane] = 0u;
        for (int w = wstart; w < 32; w++) {
            int j = w * 32 + lane;
            bool sup = false;
            if (j > i && j < TOPK) {
                float xx1 = fmaxf(ix1, bx1[j]);
                float yy1 = fmaxf(iy1, by1[j]);
                float xx2 = fminf(ix2, bx2[j]);
                float yy2 = fminf(iy2, by2[j]);
                float iw = fmaxf(xx2 - xx1, 0.0f);
                float ih = fmaxf(yy2 - yy1, 0.0f);
                float inter = iw * ih;
                float iou = inter / (iar + bar[j] - inter + 1e-8f);
                sup = (iou > IOU_TH);
            }
            u32 word = __ballot_sync(0xffffffffu, sup);
            if (lane == 0) mrow[w] = word;
        }
    }
}

// ============================================================
// Kernel 5: sequential greedy scan + output write. grid=80, block=256.
// ============================================================
#define SCAN_SMEM (TOPK * 32 * 4 + 256)
__global__ void __launch_bounds__(256)
scan_kernel(float* __restrict__ out, int out_size) {
    extern __shared__ char sm[];
    u32* maskS = (u32*)sm;
    u32* keepW = (u32*)(sm + TOPK * 32 * 4);
    const int c = blockIdx.x;
    const int tid = threadIdx.x;

    // stage class's mask slice into smem (128 KB)
    {
        const int4* src = (const int4*)(g_mask + (size_t)c * TOPK * 32);
        int4* dst = (int4*)maskS;
        for (int i = tid; i < TOPK * 8; i += 256) dst[i] = src[i];
    }
    __syncthreads();

    if (tid < 32) {
        const int lane = tid;
        u32 remv = ~g_valid[c * 32 + lane];
        u32 keep = 0;
        u32 rowreg = maskS[lane];
        for (int i = 0; i < TOPK; i++) {
            int w = i >> 5, b = i & 31;
            u32 rv = __shfl_sync(0xffffffffu, remv, w);
            u32 nxt = (i < TOPK - 1) ? maskS[(i + 1) * 32 + lane] : 0u;
            if (!((rv >> b) & 1u)) {
                remv |= rowreg;
                if (lane == w) keep |= (1u << b);
            }
            rowreg = nxt;
        }
        keepW[lane] = keep;
    }
    __syncthreads();

    for (int k = tid; k < TOPK; k += 256) {
        bool kp = (keepW[k >> 5] >> (k & 31)) & 1u;
        int o = c * KPAD + k;
        size_t ob = ((size_t)c * TOPK + k) * 5;
        if (ob + 5 <= (size_t)out_size) {
            out[ob + 0] = kp ? g_csc[o] : -1.0f;
            out[ob + 1] = kp ? g_cx1[o] : 0.0f;
            out[ob + 2] = kp ? g_cy1[o] : 0.0f;
            out[ob + 3] = kp ? g_cx2[o] : 0.0f;
            out[ob + 4] = kp ? g_cy2[o] : 0.0f;
        }
    }
}

// ============================================================
// Kernel 6: class ids (+ zero any tail)
// ============================================================
__global__ void finalize_kernel(float* __restrict__ out, int out_size) {
    int g = 400000 + blockIdx.x * blockDim.x + threadIdx.x;
    if (g < out_size) {
        if (g < 480000) out[g] = (float)((g - 400000) / 1000);
        else            out[g] = 0.0f;
    }
}

// ============================================================
extern "C" void kernel_launch(void* const* d_in, const int* in_sizes, int n_in,
                              void* d_out, int out_size) {
    const float* cls     = (const float*)d_in[0];
    const float* regr    = (const float*)d_in[1];
    const float* anchors = (const float*)d_in[2];
    const int* ph = (n_in > 3) ? (const int*)d_in[3] : nullptr;
    const int* pw = (n_in > 4) ? (const int*)d_in[4] : nullptr;
    float* out = (float*)d_out;

    static bool attr_set = false;
    if (!attr_set) {
        cudaFuncSetAttribute(scan_kernel,
                             cudaFuncAttributeMaxDynamicSharedMemorySize,
                             SCAN_SMEM);
        attr_set = true;
    }

    decode_kernel<<<(AANCH + 255) / 256, 256>>>(anchors, regr, ph, pw);
    {
        dim3 grid(APAD / 32, (NCLS + 31) / 32);
        dim3 block(32, 8);
        transpose_kernel<<<grid, block>>>(cls);
    }
    topk_kernel<<<NCLS, 512>>>();
    {
        dim3 grid(NCLS, 8);
        mask_kernel<<<grid, 256>>>();
    }
    scan_kernel<<<NCLS, 256, SCAN_SMEM>>>(out, out_size);
    if (out_size > 400000) {
        int n = out_size - 400000;
        finalize_kernel<<<(n + 255) / 256, 256>>>(out, out_size);
    }
}

// round 3
// speedup vs baseline: 4.1956x; 2.3103x over previous
#include <cuda_runtime.h>
#include <cstdint>

#define AANCH 69354
#define APAD  69376
#define AP4   (APAD / 4)          // 17344
#define NCLS  80
#define TOPK  1000
#define KPAD  1024
#define CAND  2048
#define SCORE_TH 0.05f
#define IOU_TH   0.5f
#define T1GUESS  0.1955f

typedef unsigned int u32;
typedef unsigned long long u64;

// ---- device scratch (no allocations allowed) ----
__device__ float  g_boxes[AANCH * 4];
__device__ float  g_scoresT[(size_t)NCLS * APAD];
__device__ float4 g_cbox[NCLS * KPAD];
__device__ float  g_car[NCLS * KPAD];
__device__ float  g_csc[NCLS * KPAD];
__device__ u32    g_valid[NCLS * 32];
// mask transposed: [class][word 0..31][row 0..1023]
__device__ u32    g_mask[(size_t)NCLS * 32 * 1024];

// ============================================================
// Kernel 1: decode + clip boxes
// ============================================================
__global__ void decode_kernel(const float* __restrict__ anchors,
                              const float* __restrict__ regr,
                              const int* __restrict__ ph,
                              const int* __restrict__ pw) {
    int a = blockIdx.x * blockDim.x + threadIdx.x;
    if (a >= AANCH) return;
    float W = pw ? (float)(*pw) : 608.0f;
    float H = ph ? (float)(*ph) : 608.0f;
    float4 an = ((const float4*)anchors)[a];
    float4 dl = ((const float4*)regr)[a];
    float w = an.z - an.x;
    float h = an.w - an.y;
    float cx = an.x + 0.5f * w;
    float cy = an.y + 0.5f * h;
    float dx = dl.x * 0.1f, dy = dl.y * 0.1f;
    float dw = dl.z * 0.2f, dh = dl.w * 0.2f;
    float pcx = cx + dx * w;
    float pcy = cy + dy * h;
    float pwid = expf(dw) * w;
    float phgt = expf(dh) * h;
    float x1 = fminf(fmaxf(pcx - 0.5f * pwid, 0.0f), W);
    float y1 = fminf(fmaxf(pcy - 0.5f * phgt, 0.0f), H);
    float x2 = fminf(fmaxf(pcx + 0.5f * pwid, 0.0f), W);
    float y2 = fminf(fmaxf(pcy + 0.5f * phgt, 0.0f), H);
    ((float4*)g_boxes)[a] = make_float4(x1, y1, x2, y2);
}

// ============================================================
// Kernel 2: transpose classification [A,80] -> g_scoresT [80,APAD]
// ============================================================
__global__ void transpose_kernel(const float* __restrict__ cls) {
    __shared__ float tile[32][33];
    int a0 = blockIdx.x * 32;
    int c0 = blockIdx.y * 32;
    int tx = threadIdx.x, ty = threadIdx.y;
#pragma unroll
    for (int r = 0; r < 32; r += 8) {
        int a = a0 + ty + r, c = c0 + tx;
        float v = -1.0f;
        if (a < AANCH && c < NCLS) v = cls[(size_t)a * NCLS + c];
        tile[ty + r][tx] = v;
    }
    __syncthreads();
#pragma unroll
    for (int r = 0; r < 32; r += 8) {
        int c = c0 + ty + r, a = a0 + tx;
        if (c < NCLS && a < APAD) g_scoresT[(size_t)c * APAD + a] = tile[tx][ty + r];
    }
}

// ============================================================
// Kernel 3: per-class top-1000. grid=80, block=512.
// Fast path: single-pass gather with guessed threshold, exact fallback.
// ============================================================
__device__ __forceinline__ int bin_of(float s) {
    int b = (int)((s - SCORE_TH) * (32.0f / 0.15f));
    return min(max(b, 0), 31);
}

__global__ void __launch_bounds__(512)
topk_kernel() {
    __shared__ u64 keys[CAND];
    __shared__ u32 wcnt[16];
    __shared__ u32 bincnt[32];
    __shared__ u32 wbin[16][32];
    __shared__ int s_cnt, s_valid, s_ok, s_b1, s_need, s_b2;

    const int c = blockIdx.x;
    const int tid = threadIdx.x, lane = tid & 31, warp = tid >> 5;
    const float* row = g_scoresT + (size_t)c * APAD;
    const float4* row4 = (const float4*)row;

    for (int i = tid; i < CAND; i += 512) keys[i] = 0ull;
    if (tid == 0) { s_cnt = 0; }
    __syncthreads();

    // ---- single pass: count valid + gather above T1GUESS ----
    int cnt = 0;
    for (int it = 0; it < (AP4 + 511) / 512; it++) {
        int idx = tid + it * 512;
        if (idx < AP4) {
            float4 v = row4[idx];
            int a0 = idx * 4;
            cnt += (v.x > SCORE_TH) + (v.y > SCORE_TH) +
                   (v.z > SCORE_TH) + (v.w > SCORE_TH);
            if (v.x > T1GUESS) { int p = atomicAdd(&s_cnt, 1); if (p < CAND) keys[p] = ((u64)__float_as_uint(v.x) << 32) | (u32)(~(u32)(a0 + 0)); }
            if (v.y > T1GUESS) { int p = atomicAdd(&s_cnt, 1); if (p < CAND) keys[p] = ((u64)__float_as_uint(v.y) << 32) | (u32)(~(u32)(a0 + 1)); }
            if (v.z > T1GUESS) { int p = atomicAdd(&s_cnt, 1); if (p < CAND) keys[p] = ((u64)__float_as_uint(v.z) << 32) | (u32)(~(u32)(a0 + 2)); }
            if (v.w > T1GUESS) { int p = atomicAdd(&s_cnt, 1); if (p < CAND) keys[p] = ((u64)__float_as_uint(v.w) << 32) | (u32)(~(u32)(a0 + 3)); }
        }
    }
    u32 wsum = __reduce_add_sync(0xffffffffu, (u32)cnt);
    if (lane == 0) wcnt[warp] = wsum;
    __syncthreads();
    if (tid == 0) {
        u32 tv = 0;
#pragma unroll
        for (int w = 0; w < 16; w++) tv += wcnt[w];
        s_valid = (int)tv;
        int sc = s_cnt;
        s_ok = ((sc >= TOPK && sc <= CAND) || (sc < TOPK && sc == (int)tv)) ? 1 : 0;
    }
    __syncthreads();

    // ---- fallback: exact 2-pass ballot histogram (rarely/never taken) ----
    if (!s_ok) {
        __syncthreads();
        for (int i = tid; i < CAND; i += 512) keys[i] = 0ull;
        if (tid == 0) s_cnt = 0;
        const int NITER = (APAD + 511) / 512;
        // pass 1
        {
            u32 bc = 0;
            for (int it = 0; it < NITER; it++) {
                int a = tid + it * 512;
                float s = (a < APAD) ? row[a] : -1.0f;
                bool ir = s > SCORE_TH;
                int bin = ir ? bin_of(s) : 0;
                u32 m = __ballot_sync(0xffffffffu, ir);
#pragma unroll
                for (int b = 0; b < 5; b++) {
                    u32 vb = __ballot_sync(0xffffffffu, (bin >> b) & 1);
                    m &= ((lane >> b) & 1) ? vb : ~vb;
                }
                bc += __popc(m);
            }
            wbin[warp][lane] = bc;
        }
        __syncthreads();
        if (tid < 32) {
            u32 acc = 0;
#pragma unroll
            for (int w = 0; w < 16; w++) acc += wbin[w][tid];
            bincnt[tid] = acc;
        }
        __syncthreads();
        if (tid == 0) {
            int tot = 0, b1 = 0, found = 0;
            for (int b = 31; b >= 0; b--) {
                if (tot + (int)bincnt[b] >= TOPK) { b1 = b; found = 1; break; }
                tot += (int)bincnt[b];
            }
            s_b1 = found ? b1 : 0;
            s_need = TOPK - tot;
            s_b2 = 0;
        }
        __syncthreads();
        const int b1 = s_b1;
        const float w1 = 0.15f / 32.0f;
        const float lo1 = SCORE_TH + b1 * w1;
        // pass 2
        {
            u32 bc = 0;
            for (int it = 0; it < NITER; it++) {
                int a = tid + it * 512;
                float s = (a < APAD) ? row[a] : -1.0f;
                bool ir = s > SCORE_TH;
                bool inb = ir && (bin_of(s) == b1);
                int sub = 0;
                if (inb) sub = min(max((int)((s - lo1) * (32.0f / w1)), 0), 31);
                u32 m = __ballot_sync(0xffffffffu, inb);
#pragma unroll
                for (int b = 0; b < 5; b++) {
                    u32 vb = __ballot_sync(0xffffffffu, (sub >> b) & 1);
                    m &= ((lane >> b) & 1) ? vb : ~vb;
                }
                bc += __popc(m);
            }
            wbin[warp][lane] = bc;
        }
        __syncthreads();
        if (tid < 32) {
            u32 acc = 0;
#pragma unroll
            for (int w = 0; w < 16; w++) acc += wbin[w][tid];
            bincnt[tid] = acc;
        }
        __syncthreads();
        if (tid == 0) {
            int need = s_need, tot2 = 0;
            for (int b = 31; b >= 0; b--) {
                tot2 += (int)bincnt[b];
                if (tot2 >= need) { s_b2 = b; break; }
            }
        }
        __syncthreads();
        const int b2 = s_b2;
        for (int a = tid; a < AANCH; a += 512) {
            float s = row[a];
            if (s > SCORE_TH) {
                int bin = bin_of(s);
                bool q = (bin > b1);
                if (bin == b1) {
                    int sub = min(max((int)((s - lo1) * (32.0f / w1)), 0), 31);
                    q = (sub >= b2);
                }
                if (q) {
                    int p = atomicAdd(&s_cnt, 1);
                    if (p < CAND)
                        keys[p] = ((u64)__float_as_uint(s) << 32) | (u32)(~(u32)a);
                }
            }
        }
    }
    __syncthreads();

    // ---- bitonic sort descending (score desc, idx asc) ----
    for (int k = 2; k <= CAND; k <<= 1) {
        for (int j = k >> 1; j > 0; j >>= 1) {
#pragma unroll
            for (int p = 0; p < CAND / 512; p++) {
                int i = tid + p * 512;
                int ixj = i ^ j;
                if (ixj > i) {
                    u64 va = keys[i], vb = keys[ixj];
                    bool up = ((i & k) == 0);
                    if ((va < vb) == up) { keys[i] = vb; keys[ixj] = va; }
                }
            }
            __syncthreads();
        }
    }

    // ---- write candidate table (padded to 1024 with zero boxes) ----
#pragma unroll
    for (int p = 0; p < 2; p++) {
        int k = tid + p * 512;  // 0..1023
        u64 key = keys[k];
        bool valid = (k < TOPK) && (key != 0ull);
        float sc = -1.0f;
        float4 bx = make_float4(0.f, 0.f, 0.f, 0.f);
        float ar = 0.f;
        if (valid) {
            sc = __uint_as_float((u32)(key >> 32));
            u32 a = ~(u32)key;
            bx = ((const float4*)g_boxes)[a];
            ar = __fmul_rn(__fadd_rn(bx.z, -bx.x), __fadd_rn(bx.w, -bx.y));
        }
        int o = c * KPAD + k;
        g_cbox[o] = bx;
        g_car[o] = ar;
        g_csc[o] = sc;
        u32 bal = __ballot_sync(0xffffffffu, valid);
        if (lane == 0) g_valid[c * 32 + (k >> 5)] = bal;
    }
}

// ============================================================
// Kernel 4: suppression mask, register-tiled 32x32 blocks.
// grid=(80,11), block=256 (8 warps x 6 tiles = 48 tiles/CTA; 528 tiles/class).
// Output layout: g_mask[(c*32 + w)*1024 + i]  (word w of row i).
// ============================================================
__global__ void __launch_bounds__(256)
mask_kernel() {
    __shared__ float4 bxy[KPAD];
    __shared__ float  sar[KPAD];
    const int c = blockIdx.x;
    const int tid = threadIdx.x, lane = tid & 31, warp = tid >> 5;

    for (int k = tid; k < KPAD; k += 256) {
        bxy[k] = g_cbox[c * KPAD + k];
        sar[k] = g_car[c * KPAD + k];
    }
    __syncthreads();

    const int warpGlobal = blockIdx.y * 8 + warp;   // 0..87
#pragma unroll 1
    for (int t = 0; t < 6; t++) {
        int tile = warpGlobal * 6 + t;              // 0..527
        // map tile -> (ib, w) with w >= ib (upper block-triangle)
        int ib = 0, rem = tile;
        while (rem >= 32 - ib) { rem -= 32 - ib; ib++; }
        int w = ib + rem;

        // lane's j-box in registers
        int j = w * 32 + lane;
        float4 jb = bxy[j];
        float  ja = sar[j];

        u32 myword = 0;
#pragma unroll
        for (int ii = 0; ii < 32; ii++) {
            int i = ib * 32 + ii;
            float4 ibx = bxy[i];     // broadcast
            float  ia  = sar[i];     // broadcast
            float xx1 = fmaxf(ibx.x, jb.x);
            float yy1 = fmaxf(ibx.y, jb.y);
            float xx2 = fminf(ibx.z, jb.z);
            float yy2 = fminf(ibx.w, jb.w);
            float iw = fmaxf(__fadd_rn(xx2, -xx1), 0.0f);
            float ih = fmaxf(__fadd_rn(yy2, -yy1), 0.0f);
            float inter = __fmul_rn(iw, ih);
            float tsum  = __fadd_rn(ia, ja);
            float t2    = __fadd_rn(tsum, -inter);
            float denom = __fadd_rn(t2, 1e-8f);
            float d2 = 0.5f * denom;                 // exact (power of two)
            bool sup = inter > d2;
            if (sup && __fadd_rn(inter, -d2) < 1e-6f * d2)
                sup = (__fdiv_rn(inter, denom) > IOU_TH);  // exact tie-break, ~never taken
            u32 bal = __ballot_sync(0xffffffffu, sup);
            if (lane == ii) myword = bal;
        }
        if (ib == w) myword &= (0xFFFFFFFEu << lane);  // j > i on diagonal
        g_mask[((size_t)c * 32 + w) * 1024 + ib * 32 + lane] = myword;
    }
}

// ============================================================
// Kernel 5: sequential greedy scan + output + class ids. grid=80, block=256.
// ============================================================
#define MSTRIDE 1025
#define SCAN_SMEM (32 * MSTRIDE * 4 + 256)
__global__ void __launch_bounds__(256)
scan_kernel(float* __restrict__ out, int out_size) {
    extern __shared__ char sm[];
    u32* maskS = (u32*)sm;                       // [32][1025]
    u32* keepW = (u32*)(sm + 32 * MSTRIDE * 4);
    const int c = blockIdx.x;
    const int tid = threadIdx.x;

    // stage transposed mask; zero block-lower-triangle (uncomputed tiles)
    for (int idx = tid; idx < 32 * 1024; idx += 256) {
        int w = idx >> 10, i = idx & 1023;
        u32 v = g_mask[((size_t)c * 32 + w) * 1024 + i];
        if ((i >> 5) > w) v = 0;
        maskS[w * MSTRIDE + i] = v;
    }
    __syncthreads();

    if (tid < 32) {
        const int lane = tid;
        u32 remv = ~g_valid[c * 32 + lane];
        u32 keep = 0;
        u32 rowreg = maskS[lane * MSTRIDE + 0];
        for (int i = 0; i < TOPK; i++) {
            int w = i >> 5, b = i & 31;
            u32 rv = __shfl_sync(0xffffffffu, remv, w);
            u32 nxt = maskS[lane * MSTRIDE + min(i + 1, 1023)];
            if (!((rv >> b) & 1u)) {
                remv |= rowreg;
                if (lane == w) keep |= (1u << b);
            }
            rowreg = nxt;
        }
        keepW[lane] = keep;
    }
    __syncthreads();

    for (int k = tid; k < TOPK; k += 256) {
        bool kp = (keepW[k >> 5] >> (k & 31)) & 1u;
        int o = c * KPAD + k;
        float4 b = g_cbox[o];
        size_t ob = ((size_t)c * TOPK + k) * 5;
        if (ob + 5 <= (size_t)out_size) {
            out[ob + 0] = kp ? g_csc[o] : -1.0f;
            out[ob + 1] = kp ? b.x : 0.0f;
            out[ob + 2] = kp ? b.y : 0.0f;
            out[ob + 3] = kp ? b.z : 0.0f;
            out[ob + 4] = kp ? b.w : 0.0f;
        }
        int idg = 400000 + c * TOPK + k;
        if (idg < out_size) out[idg] = (float)c;
    }
}

// ============================================================
extern "C" void kernel_launch(void* const* d_in, const int* in_sizes, int n_in,
                              void* d_out, int out_size) {
    const float* cls     = (const float*)d_in[0];
    const float* regr    = (const float*)d_in[1];
    const float* anchors = (const float*)d_in[2];
    const int* ph = (n_in > 3) ? (const int*)d_in[3] : nullptr;
    const int* pw = (n_in > 4) ? (const int*)d_in[4] : nullptr;
    float* out = (float*)d_out;

    static bool attr_set = false;
    if (!attr_set) {
        cudaFuncSetAttribute(scan_kernel,
                             cudaFuncAttributeMaxDynamicSharedMemorySize,
                             SCAN_SMEM);
        attr_set = true;
    }

    decode_kernel<<<(AANCH + 255) / 256, 256>>>(anchors, regr, ph, pw);
    {
        dim3 grid(APAD / 32, (NCLS + 31) / 32);
        dim3 block(32, 8);
        transpose_kernel<<<grid, block>>>(cls);
    }
    topk_kernel<<<NCLS, 512>>>();
    {
        dim3 grid(NCLS, 11);
        mask_kernel<<<grid, 256>>>();
    }
    scan_kernel<<<NCLS, 256, SCAN_SMEM>>>(out, out_size);
}

// round 5
// speedup vs baseline: 4.1965x; 1.0002x over previous
#include <cuda_runtime.h>
#include <cstdint>

#define AANCH 69354
#define APAD  69376
#define AP4   (APAD / 4)          // 17344
#define NCLS  80
#define TOPK  1000
#define KPAD  1024
#define CAND  2048
#define SCORE_TH 0.05f
#define IOU_TH   0.5f
#define T1GUESS  0.1955f

typedef unsigned int u32;
typedef unsigned long long u64;

// ---- device scratch (no allocations allowed) ----
__device__ float  g_boxes[AANCH * 4];
__device__ float  g_scoresT[(size_t)NCLS * APAD];
__device__ float4 g_cbox[NCLS * KPAD];
__device__ float  g_car[NCLS * KPAD];
__device__ float  g_csc[NCLS * KPAD];
__device__ u32    g_valid[NCLS * 32];
// mask transposed: [class][word 0..31][row 0..1023]
__device__ u32    g_mask[(size_t)NCLS * 32 * 1024];

// ============================================================
// Kernel 1: decode + clip boxes
// ============================================================
__global__ void decode_kernel(const float* __restrict__ anchors,
                              const float* __restrict__ regr,
                              const int* __restrict__ ph,
                              const int* __restrict__ pw) {
    int a = blockIdx.x * blockDim.x + threadIdx.x;
    if (a >= AANCH) return;
    float W = pw ? (float)(*pw) : 608.0f;
    float H = ph ? (float)(*ph) : 608.0f;
    float4 an = ((const float4*)anchors)[a];
    float4 dl = ((const float4*)regr)[a];
    float w = an.z - an.x;
    float h = an.w - an.y;
    float cx = an.x + 0.5f * w;
    float cy = an.y + 0.5f * h;
    float dx = dl.x * 0.1f, dy = dl.y * 0.1f;
    float dw = dl.z * 0.2f, dh = dl.w * 0.2f;
    float pcx = cx + dx * w;
    float pcy = cy + dy * h;
    float pwid = expf(dw) * w;
    float phgt = expf(dh) * h;
    float x1 = fminf(fmaxf(pcx - 0.5f * pwid, 0.0f), W);
    float y1 = fminf(fmaxf(pcy - 0.5f * phgt, 0.0f), H);
    float x2 = fminf(fmaxf(pcx + 0.5f * pwid, 0.0f), W);
    float y2 = fminf(fmaxf(pcy + 0.5f * phgt, 0.0f), H);
    ((float4*)g_boxes)[a] = make_float4(x1, y1, x2, y2);
}

// ============================================================
// Kernel 2: transpose classification [A,80] -> g_scoresT [80,APAD]
// ============================================================
__global__ void transpose_kernel(const float* __restrict__ cls) {
    __shared__ float tile[32][33];
    int a0 = blockIdx.x * 32;
    int c0 = blockIdx.y * 32;
    int tx = threadIdx.x, ty = threadIdx.y;
#pragma unroll
    for (int r = 0; r < 32; r += 8) {
        int a = a0 + ty + r, c = c0 + tx;
        float v = -1.0f;
        if (a < AANCH && c < NCLS) v = cls[(size_t)a * NCLS + c];
        tile[ty + r][tx] = v;
    }
    __syncthreads();
#pragma unroll
    for (int r = 0; r < 32; r += 8) {
        int c = c0 + ty + r, a = a0 + tx;
        if (c < NCLS && a < APAD) g_scoresT[(size_t)c * APAD + a] = tile[tx][ty + r];
    }
}

// ============================================================
// Kernel 3: per-class top-1000. grid=80, block=512.
// ============================================================
__device__ __forceinline__ int bin_of(float s) {
    int b = (int)((s - SCORE_TH) * (32.0f / 0.15f));
    return min(max(b, 0), 31);
}

__global__ void __launch_bounds__(512)
topk_kernel() {
    __shared__ u64 keys[CAND];
    __shared__ u32 wcnt[16];
    __shared__ u32 bincnt[32];
    __shared__ u32 wbin[16][32];
    __shared__ int s_cnt, s_valid, s_ok, s_b1, s_need, s_b2;

    const int c = blockIdx.x;
    const int tid = threadIdx.x, lane = tid & 31, warp = tid >> 5;
    const float* row = g_scoresT + (size_t)c * APAD;
    const float4* row4 = (const float4*)row;

    for (int i = tid; i < CAND; i += 512) keys[i] = 0ull;
    if (tid == 0) { s_cnt = 0; }
    __syncthreads();

    // ---- single pass: count valid + gather above T1GUESS ----
    int cnt = 0;
    for (int it = 0; it < (AP4 + 511) / 512; it++) {
        int idx = tid + it * 512;
        if (idx < AP4) {
            float4 v = row4[idx];
            int a0 = idx * 4;
            cnt += (v.x > SCORE_TH) + (v.y > SCORE_TH) +
                   (v.z > SCORE_TH) + (v.w > SCORE_TH);
            if (v.x > T1GUESS) { int p = atomicAdd(&s_cnt, 1); if (p < CAND) keys[p] = ((u64)__float_as_uint(v.x) << 32) | (u32)(~(u32)(a0 + 0)); }
            if (v.y > T1GUESS) { int p = atomicAdd(&s_cnt, 1); if (p < CAND) keys[p] = ((u64)__float_as_uint(v.y) << 32) | (u32)(~(u32)(a0 + 1)); }
            if (v.z > T1GUESS) { int p = atomicAdd(&s_cnt, 1); if (p < CAND) keys[p] = ((u64)__float_as_uint(v.z) << 32) | (u32)(~(u32)(a0 + 2)); }
            if (v.w > T1GUESS) { int p = atomicAdd(&s_cnt, 1); if (p < CAND) keys[p] = ((u64)__float_as_uint(v.w) << 32) | (u32)(~(u32)(a0 + 3)); }
        }
    }
    u32 wsum = __reduce_add_sync(0xffffffffu, (u32)cnt);
    if (lane == 0) wcnt[warp] = wsum;
    __syncthreads();
    if (tid == 0) {
        u32 tv = 0;
#pragma unroll
        for (int w = 0; w < 16; w++) tv += wcnt[w];
        s_valid = (int)tv;
        int sc = s_cnt;
        s_ok = ((sc >= TOPK && sc <= CAND) || (sc < TOPK && sc == (int)tv)) ? 1 : 0;
    }
    __syncthreads();

    // ---- fallback: exact 2-pass ballot histogram (rarely/never taken) ----
    if (!s_ok) {
        __syncthreads();
        for (int i = tid; i < CAND; i += 512) keys[i] = 0ull;
        if (tid == 0) s_cnt = 0;
        const int NITER = (APAD + 511) / 512;
        {
            u32 bc = 0;
            for (int it = 0; it < NITER; it++) {
                int a = tid + it * 512;
                float s = (a < APAD) ? row[a] : -1.0f;
                bool ir = s > SCORE_TH;
                int bin = ir ? bin_of(s) : 0;
                u32 m = __ballot_sync(0xffffffffu, ir);
#pragma unroll
                for (int b = 0; b < 5; b++) {
                    u32 vb = __ballot_sync(0xffffffffu, (bin >> b) & 1);
                    m &= ((lane >> b) & 1) ? vb : ~vb;
                }
                bc += __popc(m);
            }
            wbin[warp][lane] = bc;
        }
        __syncthreads();
        if (tid < 32) {
            u32 acc = 0;
#pragma unroll
            for (int w = 0; w < 16; w++) acc += wbin[w][tid];
            bincnt[tid] = acc;
        }
        __syncthreads();
        if (tid == 0) {
            int tot = 0, b1 = 0, found = 0;
            for (int b = 31; b >= 0; b--) {
                if (tot + (int)bincnt[b] >= TOPK) { b1 = b; found = 1; break; }
                tot += (int)bincnt[b];
            }
            s_b1 = found ? b1 : 0;
            s_need = TOPK - tot;
            s_b2 = 0;
        }
        __syncthreads();
        const int b1 = s_b1;
        const float w1 = 0.15f / 32.0f;
        const float lo1 = SCORE_TH + b1 * w1;
        {
            u32 bc = 0;
            for (int it = 0; it < NITER; it++) {
                int a = tid + it * 512;
                float s = (a < APAD) ? row[a] : -1.0f;
                bool ir = s > SCORE_TH;
                bool inb = ir && (bin_of(s) == b1);
                int sub = 0;
                if (inb) sub = min(max((int)((s - lo1) * (32.0f / w1)), 0), 31);
                u32 m = __ballot_sync(0xffffffffu, inb);
#pragma unroll
                for (int b = 0; b < 5; b++) {
                    u32 vb = __ballot_sync(0xffffffffu, (sub >> b) & 1);
                    m &= ((lane >> b) & 1) ? vb : ~vb;
                }
                bc += __popc(m);
            }
            wbin[warp][lane] = bc;
        }
        __syncthreads();
        if (tid < 32) {
            u32 acc = 0;
#pragma unroll
            for (int w = 0; w < 16; w++) acc += wbin[w][tid];
            bincnt[tid] = acc;
        }
        __syncthreads();
        if (tid == 0) {
            int need = s_need, tot2 = 0;
            for (int b = 31; b >= 0; b--) {
                tot2 += (int)bincnt[b];
                if (tot2 >= need) { s_b2 = b; break; }
            }
        }
        __syncthreads();
        const int b2 = s_b2;
        for (int a = tid; a < AANCH; a += 512) {
            float s = row[a];
            if (s > SCORE_TH) {
                int bin = bin_of(s);
                bool q = (bin > b1);
                if (bin == b1) {
                    int sub = min(max((int)((s - lo1) * (32.0f / w1)), 0), 31);
                    q = (sub >= b2);
                }
                if (q) {
                    int p = atomicAdd(&s_cnt, 1);
                    if (p < CAND)
                        keys[p] = ((u64)__float_as_uint(s) << 32) | (u32)(~(u32)a);
                }
            }
        }
    }
    __syncthreads();

    // ---- bitonic sort descending (score desc, idx asc) ----
    for (int k = 2; k <= CAND; k <<= 1) {
        for (int j = k >> 1; j > 0; j >>= 1) {
#pragma unroll
            for (int p = 0; p < CAND / 512; p++) {
                int i = tid + p * 512;
                int ixj = i ^ j;
                if (ixj > i) {
                    u64 va = keys[i], vb = keys[ixj];
                    bool up = ((i & k) == 0);
                    if ((va < vb) == up) { keys[i] = vb; keys[ixj] = va; }
                }
            }
            __syncthreads();
        }
    }

    // ---- write candidate table (padded to 1024 with zero boxes) ----
#pragma unroll
    for (int p = 0; p < 2; p++) {
        int k = tid + p * 512;  // 0..1023
        u64 key = keys[k];
        bool valid = (k < TOPK) && (key != 0ull);
        float sc = -1.0f;
        float4 bx = make_float4(0.f, 0.f, 0.f, 0.f);
        float ar = 0.f;
        if (valid) {
            sc = __uint_as_float((u32)(key >> 32));
            u32 a = ~(u32)key;
            bx = ((const float4*)g_boxes)[a];
            ar = __fmul_rn(__fadd_rn(bx.z, -bx.x), __fadd_rn(bx.w, -bx.y));
        }
        int o = c * KPAD + k;
        g_cbox[o] = bx;
        g_car[o] = ar;
        g_csc[o] = sc;
        u32 bal = __ballot_sync(0xffffffffu, valid);
        if (lane == 0) g_valid[c * 32 + (k >> 5)] = bal;
    }
}

// ============================================================
// Kernel 4: suppression mask, lane-owns-row, no ballot.
// grid=(80,11), block=256. 8 warps x 6 tiles = 48 tiles/CTA, 528/class.
// Lane l of tile (ib,w) owns row i=ib*32+l; assembles word w of row i.
// ============================================================
__global__ void __launch_bounds__(256)
mask_kernel() {
    __shared__ float4 bxy[KPAD];
    __shared__ float  sar[KPAD];
    const int c = blockIdx.x;
    const int tid = threadIdx.x, lane = tid & 31, warp = tid >> 5;

    for (int k = tid; k < KPAD; k += 256) {
        bxy[k] = g_cbox[c * KPAD + k];
        sar[k] = g_car[c * KPAD + k];
    }
    __syncthreads();

    const int warpGlobal = blockIdx.y * 8 + warp;   // 0..87
#pragma unroll 1
    for (int t = 0; t < 6; t++) {
        int tile = warpGlobal * 6 + t;              // 0..527
        // closed-form tile -> (ib, w), w >= ib:
        // C(ib) = ib*(65-ib)/2 tiles before row-block ib
        int ib = (int)((65.0f - sqrtf(fmaxf(4225.0f - 8.0f * (float)tile, 0.0f))) * 0.5f);
        while (ib > 0 && ib * (65 - ib) / 2 > tile) ib--;
        while ((ib + 1) * (64 - ib) / 2 <= tile) ib++;
        int w = ib + (tile - ib * (65 - ib) / 2);

        // lane's own i-box in registers
        int i = ib * 32 + lane;
        float4 ibx = bxy[i];
        float  ia  = sar[i];

        u32 myword = 0;
        const int jbase = w * 32;
#pragma unroll
        for (int jj = 0; jj < 32; jj++) {
            float4 jb = bxy[jbase + jj];   // broadcast
            float  ja = sar[jbase + jj];   // broadcast
            float xx1 = fmaxf(ibx.x, jb.x);
            float yy1 = fmaxf(ibx.y, jb.y);
            float xx2 = fminf(ibx.z, jb.z);
            float yy2 = fminf(ibx.w, jb.w);
            float iw = fmaxf(__fadd_rn(xx2, -xx1), 0.0f);
            float ih = fmaxf(__fadd_rn(yy2, -yy1), 0.0f);
            float inter = __fmul_rn(iw, ih);
            float tsum  = __fadd_rn(ia, ja);
            float t2    = __fadd_rn(tsum, -inter);
            float denom = __fadd_rn(t2, 1e-8f);
            float d2 = 0.5f * denom;                 // exact
            bool sup = inter > d2;
            if (sup) {
                if (__fadd_rn(inter, -d2) < 1e-6f * d2)
                    sup = (__fdiv_rn(inter, denom) > IOU_TH);  // exact near-tie
                if (sup) myword |= (1u << jj);
            }
        }
        if (ib == w) myword &= (0xFFFFFFFEu << lane);  // only j > i on diagonal
        g_mask[((size_t)c * 32 + w) * 1024 + ib * 32 + lane] = myword;
    }
}

// ============================================================
// Kernel 5: blocked greedy scan + output + class ids. grid=80, block=256.
// 32 blocks of 32 candidates; lane0 resolves intra-block with registers,
// all lanes update remv with independent predicated loads (L2-resident mask).
// ============================================================
#define GETW(buf, ii) (((ii) & 3) == 0 ? buf[(ii) >> 2].x : \
                       ((ii) & 3) == 1 ? buf[(ii) >> 2].y : \
                       ((ii) & 3) == 2 ? buf[(ii) >> 2].z : buf[(ii) >> 2].w)

__global__ void __launch_bounds__(256)
scan_kernel(float* __restrict__ out, int out_size) {
    __shared__ u32 s_keep[32];
    const int c = blockIdx.x;
    const int tid = threadIdx.x;
    const u32* mbase = g_mask + (size_t)c * 32 * 1024;

    if (tid < 32) {
        const int lane = tid;
        u32 remv = ~g_valid[c * 32 + lane];
        u32 keeplane = 0;

        uint4 cur[8], nxt[8];
        // diag tile lives only in lane 0's registers
        if (lane == 0) {
            const uint4* d = (const uint4*)(mbase + 0);
#pragma unroll
            for (int q = 0; q < 8; q++) cur[q] = d[q];
        }
#pragma unroll 1
        for (int w = 0; w < 32; w++) {
            // prefetch next diag early (independent of resolve)
            if (lane == 0 && w < 31) {
                const uint4* d = (const uint4*)(mbase + (w + 1) * 1024 + (w + 1) * 32);
#pragma unroll
                for (int q = 0; q < 8; q++) nxt[q] = d[q];
            }
            u32 rv = __shfl_sync(0xffffffffu, remv, w);
            u32 kept = 0;
            if (lane == 0) {
                u32 keep = ~rv;
#pragma unroll
                for (int ii = 0; ii < 32; ii++) {
                    if ((keep >> ii) & 1u) {
                        kept |= (1u << ii);
                        keep &= ~GETW(cur, ii);
                    }
                }
            }
            kept = __shfl_sync(0xffffffffu, kept, 0);
            if (lane == w) keeplane = kept;
            // update remv (only words > w are needed later)
            if (lane > w) {
                const u32* col = mbase + lane * 1024 + w * 32;
#pragma unroll
                for (int ii = 0; ii < 32; ii++) {
                    if ((kept >> ii) & 1u) remv |= col[ii];
                }
            }
            if (lane == 0) {
#pragma unroll
                for (int q = 0; q < 8; q++) cur[q] = nxt[q];
            }
        }
        s_keep[tid] = keeplane;
    }
    __syncthreads();

    for (int k = tid; k < TOPK; k += 256) {
        bool kp = (s_keep[k >> 5] >> (k & 31)) & 1u;
        int o = c * KPAD + k;
        float4 b = g_cbox[o];
        size_t ob = ((size_t)c * TOPK + k) * 5;
        if (ob + 5 <= (size_t)out_size) {
            out[ob + 0] = kp ? g_csc[o] : -1.0f;
            out[ob + 1] = kp ? b.x : 0.0f;
            out[ob + 2] = kp ? b.y : 0.0f;
            out[ob + 3] = kp ? b.z : 0.0f;
            out[ob + 4] = kp ? b.w : 0.0f;
        }
        int idg = 400000 + c * TOPK + k;
        if (idg < out_size) out[idg] = (float)c;
    }
}

// ============================================================
extern "C" void kernel_launch(void* const* d_in, const int* in_sizes, int n_in,
                              void* d_out, int out_size) {
    const float* cls     = (const float*)d_in[0];
    const float* regr    = (const float*)d_in[1];
    const float* anchors = (const float*)d_in[2];
    const int* ph = (n_in > 3) ? (const int*)d_in[3] : nullptr;
    const int* pw = (n_in > 4) ? (const int*)d_in[4] : nullptr;
    float* out = (float*)d_out;

    decode_kernel<<<(AANCH + 255) / 256, 256>>>(anchors, regr, ph, pw);
    {
        dim3 grid(APAD / 32, (NCLS + 31) / 32);
        dim3 block(32, 8);
        transpose_kernel<<<grid, block>>>(cls);
    }
    topk_kernel<<<NCLS, 512>>>();
    {
        dim3 grid(NCLS, 11);
        mask_kernel<<<grid, 256>>>();
    }
    scan_kernel<<<NCLS, 256>>>(out, out_size);
}